// round 7
// baseline (speedup 1.0000x reference)
#include <cuda_runtime.h>

#define Bsz 4
#define Tsz 2048
#define Csz 1024
#define Hn  16
#define Dh  64
#define BT  (Bsz * Tsz)     /* 8192 */
#define N3  (3 * Csz)       /* 3072 */

// Scratch (allocation-free rule: __device__ globals)
__device__ float g_q[Bsz * Hn * Tsz * Dh];   // [B,H,T,D]
__device__ float g_k[Bsz * Hn * Tsz * Dh];
__device__ float g_v[Bsz * Hn * Tsz * Dh];
__device__ float g_y[BT * Csz];              // [B,T,C] attention output

// ---------------------------------------------------------------------------
// GEMM 1: qkv = x @ w_attn + b_attn, scattered into g_q/g_k/g_v ([B,H,T,D])
// 128x128x8 tile, 256 threads, 8x8 per thread. (R1-proven; + minBlocks=2)
// ---------------------------------------------------------------------------
__global__ __launch_bounds__(256, 2) void qkv_gemm(const float* __restrict__ A,
                                                   const float* __restrict__ Bw,
                                                   const float* __restrict__ bias)
{
    __shared__ float As[8][128];
    __shared__ float Bs[8][128];

    const int tid = threadIdx.x;
    const int bm = blockIdx.y * 128;
    const int bn = blockIdx.x * 128;
    const int tr = (tid >> 4) * 8;    // 0..120
    const int tc = (tid & 15) * 8;    // 0..120

    float acc[8][8];
#pragma unroll
    for (int i = 0; i < 8; i++)
#pragma unroll
        for (int j = 0; j < 8; j++) acc[i][j] = 0.f;

    const int arow = tid >> 1;            // 0..127
    const int acol = (tid & 1) * 4;       // 0 or 4
    const int brow = tid >> 5;            // 0..7
    const int bcol = (tid & 31) * 4;      // 0..124

    const float* Ap = A + (bm + arow) * Csz + acol;
    const float* Bp = Bw + brow * N3 + bn + bcol;

    for (int k0 = 0; k0 < Csz; k0 += 8) {
        float4 a4 = *(const float4*)(Ap + k0);
        float4 b4 = *(const float4*)(Bp + k0 * N3);
        As[acol + 0][arow] = a4.x;
        As[acol + 1][arow] = a4.y;
        As[acol + 2][arow] = a4.z;
        As[acol + 3][arow] = a4.w;
        *(float4*)&Bs[brow][bcol] = b4;
        __syncthreads();
#pragma unroll
        for (int kk = 0; kk < 8; kk++) {
            float af[8], bf[8];
#pragma unroll
            for (int i = 0; i < 8; i++) af[i] = As[kk][tr + i];
#pragma unroll
            for (int j = 0; j < 8; j++) bf[j] = Bs[kk][tc + j];
#pragma unroll
            for (int i = 0; i < 8; i++)
#pragma unroll
                for (int j = 0; j < 8; j++) acc[i][j] += af[i] * bf[j];
        }
        __syncthreads();
    }

    // Epilogue: bias + scatter to q/k/v in [B,H,T,D]
#pragma unroll
    for (int i = 0; i < 8; i++) {
        const int m = bm + tr + i;
        const int b = m >> 11;           // /T
        const int t = m & (Tsz - 1);
#pragma unroll
        for (int j = 0; j < 8; j++) {
            const int n = bn + tc + j;
            const float val = acc[i][j] + bias[n];
            const int sec = n >> 10;     // 0=q,1=k,2=v
            const int c2 = n & 1023;
            const int h = c2 >> 6;
            const int d = c2 & 63;
            float* dst = (sec == 0) ? g_q : (sec == 1) ? g_k : g_v;
            dst[((b * Hn + h) * Tsz + t) * Dh + d] = val;
        }
    }
}

// ---------------------------------------------------------------------------
// GEMM 2: out = y @ w_proj + b_proj   (R1-proven; + minBlocks=2)
// ---------------------------------------------------------------------------
__global__ __launch_bounds__(256, 2) void proj_gemm(const float* __restrict__ Bw,
                                                    const float* __restrict__ bias,
                                                    float* __restrict__ out)
{
    __shared__ float As[8][128];
    __shared__ float Bs[8][128];

    const int tid = threadIdx.x;
    const int bm = blockIdx.y * 128;
    const int bn = blockIdx.x * 128;
    const int tr = (tid >> 4) * 8;
    const int tc = (tid & 15) * 8;

    float acc[8][8];
#pragma unroll
    for (int i = 0; i < 8; i++)
#pragma unroll
        for (int j = 0; j < 8; j++) acc[i][j] = 0.f;

    const int arow = tid >> 1;
    const int acol = (tid & 1) * 4;
    const int brow = tid >> 5;
    const int bcol = (tid & 31) * 4;

    const float* Ap = g_y + (bm + arow) * Csz + acol;
    const float* Bp = Bw + brow * Csz + bn + bcol;

    for (int k0 = 0; k0 < Csz; k0 += 8) {
        float4 a4 = *(const float4*)(Ap + k0);
        float4 b4 = *(const float4*)(Bp + k0 * Csz);
        As[acol + 0][arow] = a4.x;
        As[acol + 1][arow] = a4.y;
        As[acol + 2][arow] = a4.z;
        As[acol + 3][arow] = a4.w;
        *(float4*)&Bs[brow][bcol] = b4;
        __syncthreads();
#pragma unroll
        for (int kk = 0; kk < 8; kk++) {
            float af[8], bf[8];
#pragma unroll
            for (int i = 0; i < 8; i++) af[i] = As[kk][tr + i];
#pragma unroll
            for (int j = 0; j < 8; j++) bf[j] = Bs[kk][tc + j];
#pragma unroll
            for (int i = 0; i < 8; i++)
#pragma unroll
                for (int j = 0; j < 8; j++) acc[i][j] += af[i] * bf[j];
        }
        __syncthreads();
    }

#pragma unroll
    for (int i = 0; i < 8; i++) {
        const int m = bm + tr + i;
#pragma unroll
        for (int j = 0; j < 8; j++) {
            const int n = bn + tc + j;
            out[m * Csz + n] = acc[i][j] + bias[n];
        }
    }
}

// ---------------------------------------------------------------------------
// Flash attention (fp32, causal). Q tile 128, K tile 64, 256 threads,
// per-thread 8x4 micro-tiles. Same stride-65 layout conventions as R1,
// but P has its own buffer (no aliasing) and Q tile is 2x taller:
//   - FMA:LDS ratio 2.0 -> 2.67
//   - K/V staging traffic and tile iterations halved
// Smem: Qs[128][65] + Ks[64][65] + Vs[64][65] + Ps[128][65] = 99840 B (dyn).
// ---------------------------------------------------------------------------
extern __shared__ float sm_attn[];

__global__ __launch_bounds__(256, 2) void attn_kernel()
{
    float* Qs = sm_attn;                 // [128][65], pre-scaled by 1/8
    float* Ks = Qs + 128 * 65;           // [64][65]
    float* Vs = Ks + 64 * 65;            // [64][65]
    float* Ps = Vs + 64 * 65;            // [128][65]

    const int head = blockIdx.y;         // b*H + h
    const int qt = blockIdx.x;           // query tile (128 rows)
    const float* Qg = g_q + head * (Tsz * Dh);
    const float* Kg = g_k + head * (Tsz * Dh);
    const float* Vg = g_v + head * (Tsz * Dh);

    const int tid = threadIdx.x;
    const int rg = tid >> 4;             // 0..15 row group (8 rows each)
    const int cg = tid & 15;             // 0..15 col group (4 cols each)
    const int r0 = rg * 8;
    const int c0 = cg * 4;

    float m_i[8], l_i[8], o[8][4];
#pragma unroll
    for (int i = 0; i < 8; i++) {
        m_i[i] = -1e30f;
        l_i[i] = 0.f;
#pragma unroll
        for (int j = 0; j < 4; j++) o[i][j] = 0.f;
    }

    // Load Q tile 128x64 (scale folded in: 1/sqrt(64) = 0.125)
#pragma unroll
    for (int j = 0; j < 8; j++) {
        const int f4 = tid + j * 256;          // 2048 float4
        const int r = f4 >> 4, c = (f4 & 15) * 4;
        float4 v = *(const float4*)(Qg + (size_t)(qt * 128 + r) * 64 + c);
        Qs[r * 65 + c + 0] = v.x * 0.125f;
        Qs[r * 65 + c + 1] = v.y * 0.125f;
        Qs[r * 65 + c + 2] = v.z * 0.125f;
        Qs[r * 65 + c + 3] = v.w * 0.125f;
    }

    const int ktmax = 2 * qt + 1;
    for (int kt = 0; kt <= ktmax; kt++) {
        __syncthreads();   // Q staged (first it); prior S/PV done with Ks/Vs
#pragma unroll
        for (int j = 0; j < 4; j++) {
            const int f4 = tid + j * 256;      // 1024 float4 = 64x64
            const int r = f4 >> 4, c = (f4 & 15) * 4;
            float4 kv = *(const float4*)(Kg + (size_t)(kt * 64 + r) * 64 + c);
            float4 vv = *(const float4*)(Vg + (size_t)(kt * 64 + r) * 64 + c);
            Ks[r * 65 + c + 0] = kv.x;
            Ks[r * 65 + c + 1] = kv.y;
            Ks[r * 65 + c + 2] = kv.z;
            Ks[r * 65 + c + 3] = kv.w;
            Vs[r * 65 + c + 0] = vv.x;
            Vs[r * 65 + c + 1] = vv.y;
            Vs[r * 65 + c + 2] = vv.z;
            Vs[r * 65 + c + 3] = vv.w;
        }
        __syncthreads();

        // S = Q @ K^T (128x64 tile, 8x4 per thread)
        float s[8][4];
#pragma unroll
        for (int i = 0; i < 8; i++)
#pragma unroll
            for (int j = 0; j < 4; j++) s[i][j] = 0.f;

        for (int dd = 0; dd < 64; dd++) {
            float af[8], bf[4];
#pragma unroll
            for (int i = 0; i < 8; i++) af[i] = Qs[(r0 + i) * 65 + dd];
#pragma unroll
            for (int j = 0; j < 4; j++) bf[j] = Ks[(c0 + j) * 65 + dd];
#pragma unroll
            for (int i = 0; i < 8; i++)
#pragma unroll
                for (int j = 0; j < 4; j++) s[i][j] += af[i] * bf[j];
        }

        // Causal mask — only the last two K tiles can cross the diagonal
        if (kt >= 2 * qt) {
            const int rowb = qt * 128 + r0;
            const int colb = kt * 64 + c0;
#pragma unroll
            for (int i = 0; i < 8; i++)
#pragma unroll
                for (int j = 0; j < 4; j++)
                    if (colb + j > rowb + i) s[i][j] = -1e30f;
        }

        // Online softmax; rows shared by 16 consecutive lanes (half-warp)
#pragma unroll
        for (int i = 0; i < 8; i++) {
            float tmax = s[i][0];
#pragma unroll
            for (int j = 1; j < 4; j++) tmax = fmaxf(tmax, s[i][j]);
#pragma unroll
            for (int off = 1; off < 16; off <<= 1)
                tmax = fmaxf(tmax, __shfl_xor_sync(0xffffffffu, tmax, off));

            const float mnew = fmaxf(m_i[i], tmax);
            const float sc = __expf(m_i[i] - mnew);
            m_i[i] = mnew;

            float tsum = 0.f;
#pragma unroll
            for (int j = 0; j < 4; j++) {
                const float p = __expf(s[i][j] - mnew);
                s[i][j] = p;
                tsum += p;
            }
#pragma unroll
            for (int off = 1; off < 16; off <<= 1)
                tsum += __shfl_xor_sync(0xffffffffu, tsum, off);

            l_i[i] = l_i[i] * sc + tsum;
#pragma unroll
            for (int j = 0; j < 4; j++) {
                o[i][j] *= sc;
                Ps[(r0 + i) * 65 + (c0 + j)] = s[i][j];
            }
        }
        // P rows are produced and consumed by the same half-warp; warp sync
        // is sufficient for visibility.
        __syncwarp();

        // O += P @ V
        for (int kk = 0; kk < 64; kk++) {
            float af[8], bf[4];
#pragma unroll
            for (int i = 0; i < 8; i++) af[i] = Ps[(r0 + i) * 65 + kk];
#pragma unroll
            for (int j = 0; j < 4; j++) bf[j] = Vs[kk * 65 + c0 + j];
#pragma unroll
            for (int i = 0; i < 8; i++)
#pragma unroll
                for (int j = 0; j < 4; j++) o[i][j] += af[i] * bf[j];
        }
    }

    // Write y in [B,T,C] (head h occupies cols h*64..h*64+63)
    const int b = head >> 4;
    const int h = head & 15;
#pragma unroll
    for (int i = 0; i < 8; i++) {
        const int t = qt * 128 + r0 + i;
        const float inv = 1.f / l_i[i];
#pragma unroll
        for (int j = 0; j < 4; j++)
            g_y[((size_t)b * Tsz + t) * Csz + h * 64 + c0 + j] = o[i][j] * inv;
    }
}

// ---------------------------------------------------------------------------

extern "C" void kernel_launch(void* const* d_in, const int* in_sizes, int n_in,
                              void* d_out, int out_size)
{
    (void)in_sizes; (void)n_in; (void)out_size;
    const float* x      = (const float*)d_in[0];
    const float* w_attn = (const float*)d_in[1];
    const float* b_attn = (const float*)d_in[2];
    const float* w_proj = (const float*)d_in[3];
    const float* b_proj = (const float*)d_in[4];
    float* out = (float*)d_out;

    // 99840 B dynamic smem; attribute-set mechanism proven in Round 1.
    static const size_t ATTN_SMEM =
        (size_t)(128 * 65 + 64 * 65 + 64 * 65 + 128 * 65) * sizeof(float);
    cudaFuncSetAttribute(attn_kernel,
                         cudaFuncAttributeMaxDynamicSharedMemorySize,
                         (int)ATTN_SMEM);

    qkv_gemm<<<dim3(N3 / 128, BT / 128), 256>>>(x, w_attn, b_attn);
    attn_kernel<<<dim3(Tsz / 128, Bsz * Hn), 256, ATTN_SMEM>>>();
    proj_gemm<<<dim3(Csz / 128, BT / 128), 256>>>(w_proj, b_proj, out);
}

// round 10
// speedup vs baseline: 1.0821x; 1.0821x over previous
#include <cuda_runtime.h>

#define Bsz 4
#define Tsz 2048
#define Csz 1024
#define Hn  16
#define Dh  64
#define BT  (Bsz * Tsz)     /* 8192 */
#define N3  (3 * Csz)       /* 3072 */

// Scratch (allocation-free rule: __device__ globals)
__device__ float g_q[Bsz * Hn * Tsz * Dh];   // [B,H,T,D]
__device__ float g_k[Bsz * Hn * Tsz * Dh];
__device__ float g_v[Bsz * Hn * Tsz * Dh];
__device__ float g_y[BT * Csz];              // [B,T,C] attention output

// ---------------------------------------------------------------------------
// GEMM 1 (NON-template): qkv = x @ w_attn + b_attn, scatter to g_q/g_k/g_v.
// 128x128x8 tiles, 256 thr, 8 rows x (4+4 split) cols per thread.
// Double-buffered smem; B-fragment reads are contiguous float4s.
// ---------------------------------------------------------------------------
__global__ __launch_bounds__(256) void qkv_gemm(const float* __restrict__ A,
                                                const float* __restrict__ Bw,
                                                const float* __restrict__ bias)
{
    __shared__ float As[2][8][128];
    __shared__ float Bs[2][8][128];

    const int tid = threadIdx.x;
    const int bm = blockIdx.y * 128;
    const int bn = blockIdx.x * 128;
    const int tr  = (tid >> 4) * 8;
    const int tc0 = (tid & 15) * 4;      // col group 0; group 1 = tc0 + 64

    float acc[8][8];
#pragma unroll
    for (int i = 0; i < 8; i++)
#pragma unroll
        for (int j = 0; j < 8; j++) acc[i][j] = 0.f;

    const int arow = tid >> 1;
    const int acol = (tid & 1) * 4;
    const int brow = tid >> 5;
    const int bcol = (tid & 31) * 4;

    const float* Ap = A + (size_t)(bm + arow) * Csz + acol;
    const float* Bp = Bw + (size_t)brow * N3 + bn + bcol;

    {   // prologue: chunk 0 -> buffer 0
        float4 a4 = *(const float4*)(Ap);
        float4 b4 = *(const float4*)(Bp);
        As[0][acol + 0][arow] = a4.x;
        As[0][acol + 1][arow] = a4.y;
        As[0][acol + 2][arow] = a4.z;
        As[0][acol + 3][arow] = a4.w;
        *(float4*)&Bs[0][brow][bcol] = b4;
    }
    __syncthreads();

    const int NC = Csz / 8;
    for (int c = 0; c < NC; c++) {
        const int cur = c & 1;
        float4 a4, b4;
        if (c + 1 < NC) {
            a4 = *(const float4*)(Ap + (c + 1) * 8);
            b4 = *(const float4*)(Bp + (size_t)(c + 1) * 8 * N3);
        }

#pragma unroll
        for (int kk = 0; kk < 8; kk++) {
            float4 af0 = *(const float4*)&As[cur][kk][tr];
            float4 af1 = *(const float4*)&As[cur][kk][tr + 4];
            const float af[8] = {af0.x, af0.y, af0.z, af0.w,
                                 af1.x, af1.y, af1.z, af1.w};
            float4 bg0 = *(const float4*)&Bs[cur][kk][tc0];
            float4 bg1 = *(const float4*)&Bs[cur][kk][tc0 + 64];
            const float bf[8] = {bg0.x, bg0.y, bg0.z, bg0.w,
                                 bg1.x, bg1.y, bg1.z, bg1.w};
#pragma unroll
            for (int i = 0; i < 8; i++)
#pragma unroll
                for (int j = 0; j < 8; j++) acc[i][j] += af[i] * bf[j];
        }

        if (c + 1 < NC) {
            const int nxt = cur ^ 1;
            As[nxt][acol + 0][arow] = a4.x;
            As[nxt][acol + 1][arow] = a4.y;
            As[nxt][acol + 2][arow] = a4.z;
            As[nxt][acol + 3][arow] = a4.w;
            *(float4*)&Bs[nxt][brow][bcol] = b4;
        }
        __syncthreads();
    }

#pragma unroll
    for (int i = 0; i < 8; i++) {
        const int row = bm + tr + i;
        const int bb = row >> 11;
        const int t  = row & (Tsz - 1);
#pragma unroll
        for (int j = 0; j < 8; j++) {
            const int n = bn + ((j < 4) ? (tc0 + j) : (tc0 + 60 + j));  // +64+(j-4)
            const float val = acc[i][j] + bias[n];
            const int sec = n >> 10;
            const int c2  = n & 1023;
            const int h = c2 >> 6;
            const int d = c2 & 63;
            float* dst = (sec == 0) ? g_q : (sec == 1) ? g_k : g_v;
            dst[((bb * Hn + h) * Tsz + t) * Dh + d] = val;
        }
    }
}

// ---------------------------------------------------------------------------
// GEMM 2 (NON-template): out = y @ w_proj + b_proj. Same structure.
// ---------------------------------------------------------------------------
__global__ __launch_bounds__(256) void proj_gemm(const float* __restrict__ Bw,
                                                 const float* __restrict__ bias,
                                                 float* __restrict__ out)
{
    __shared__ float As[2][8][128];
    __shared__ float Bs[2][8][128];

    const int tid = threadIdx.x;
    const int bm = blockIdx.y * 128;
    const int bn = blockIdx.x * 128;
    const int tr  = (tid >> 4) * 8;
    const int tc0 = (tid & 15) * 4;

    float acc[8][8];
#pragma unroll
    for (int i = 0; i < 8; i++)
#pragma unroll
        for (int j = 0; j < 8; j++) acc[i][j] = 0.f;

    const int arow = tid >> 1;
    const int acol = (tid & 1) * 4;
    const int brow = tid >> 5;
    const int bcol = (tid & 31) * 4;

    const float* Ap = g_y + (size_t)(bm + arow) * Csz + acol;
    const float* Bp = Bw + (size_t)brow * Csz + bn + bcol;

    {
        float4 a4 = *(const float4*)(Ap);
        float4 b4 = *(const float4*)(Bp);
        As[0][acol + 0][arow] = a4.x;
        As[0][acol + 1][arow] = a4.y;
        As[0][acol + 2][arow] = a4.z;
        As[0][acol + 3][arow] = a4.w;
        *(float4*)&Bs[0][brow][bcol] = b4;
    }
    __syncthreads();

    const int NC = Csz / 8;
    for (int c = 0; c < NC; c++) {
        const int cur = c & 1;
        float4 a4, b4;
        if (c + 1 < NC) {
            a4 = *(const float4*)(Ap + (c + 1) * 8);
            b4 = *(const float4*)(Bp + (size_t)(c + 1) * 8 * Csz);
        }

#pragma unroll
        for (int kk = 0; kk < 8; kk++) {
            float4 af0 = *(const float4*)&As[cur][kk][tr];
            float4 af1 = *(const float4*)&As[cur][kk][tr + 4];
            const float af[8] = {af0.x, af0.y, af0.z, af0.w,
                                 af1.x, af1.y, af1.z, af1.w};
            float4 bg0 = *(const float4*)&Bs[cur][kk][tc0];
            float4 bg1 = *(const float4*)&Bs[cur][kk][tc0 + 64];
            const float bf[8] = {bg0.x, bg0.y, bg0.z, bg0.w,
                                 bg1.x, bg1.y, bg1.z, bg1.w};
#pragma unroll
            for (int i = 0; i < 8; i++)
#pragma unroll
                for (int j = 0; j < 8; j++) acc[i][j] += af[i] * bf[j];
        }

        if (c + 1 < NC) {
            const int nxt = cur ^ 1;
            As[nxt][acol + 0][arow] = a4.x;
            As[nxt][acol + 1][arow] = a4.y;
            As[nxt][acol + 2][arow] = a4.z;
            As[nxt][acol + 3][arow] = a4.w;
            *(float4*)&Bs[nxt][brow][bcol] = b4;
        }
        __syncthreads();
    }

#pragma unroll
    for (int i = 0; i < 8; i++) {
        const int row = bm + tr + i;
#pragma unroll
        for (int j = 0; j < 8; j++) {
            const int n = bn + ((j < 4) ? (tc0 + j) : (tc0 + 60 + j));
            out[(size_t)row * Csz + n] = acc[i][j] + bias[n];
        }
    }
}

// ---------------------------------------------------------------------------
// Flash attention — VERBATIM from the PASSING Round-1 kernel (fp32 FFMA).
// ---------------------------------------------------------------------------
extern __shared__ float sm_attn[];

__global__ __launch_bounds__(256) void attn_kernel()
{
    float* Qs = sm_attn;                 // [64][64], pre-scaled by 1/8
    float* Ks = sm_attn + 64 * 64;       // [64][65]; later holds P
    float* Vs = Ks + 64 * 65;            // [64][64]

    const int head = blockIdx.y;
    const int qt = blockIdx.x;
    const float* Qg = g_q + head * (Tsz * Dh);
    const float* Kg = g_k + head * (Tsz * Dh);
    const float* Vg = g_v + head * (Tsz * Dh);

    const int tid = threadIdx.x;
    const int rg = tid >> 4;
    const int cg = tid & 15;
    const int r0 = rg * 4;
    const int c0 = cg * 4;

    float m_i[4], l_i[4], o[4][4];
#pragma unroll
    for (int i = 0; i < 4; i++) {
        m_i[i] = -1e30f;
        l_i[i] = 0.f;
#pragma unroll
        for (int j = 0; j < 4; j++) o[i][j] = 0.f;
    }

    for (int i = tid; i < 64 * 64; i += 256) {
        const int r = i >> 6, d = i & 63;
        Qs[r * 64 + d] = Qg[(qt * 64 + r) * 64 + d] * 0.125f;
    }

    for (int kt = 0; kt <= qt; kt++) {
        __syncthreads();
        for (int i = tid; i < 64 * 64; i += 256) {
            const int r = i >> 6, d = i & 63;
            Ks[r * 65 + d] = Kg[(kt * 64 + r) * 64 + d];
            Vs[r * 64 + d] = Vg[(kt * 64 + r) * 64 + d];
        }
        __syncthreads();

        float s[4][4];
#pragma unroll
        for (int i = 0; i < 4; i++)
#pragma unroll
            for (int j = 0; j < 4; j++) s[i][j] = 0.f;

        for (int dd = 0; dd < 64; dd++) {
            float af[4], bf[4];
#pragma unroll
            for (int i = 0; i < 4; i++) af[i] = Qs[(r0 + i) * 64 + dd];
#pragma unroll
            for (int j = 0; j < 4; j++) bf[j] = Ks[(c0 + j) * 65 + dd];
#pragma unroll
            for (int i = 0; i < 4; i++)
#pragma unroll
                for (int j = 0; j < 4; j++) s[i][j] += af[i] * bf[j];
        }

        if (kt == qt) {
#pragma unroll
            for (int i = 0; i < 4; i++)
#pragma unroll
                for (int j = 0; j < 4; j++)
                    if (c0 + j > r0 + i) s[i][j] = -1e30f;
        }

        __syncthreads();

#pragma unroll
        for (int i = 0; i < 4; i++) {
            float tmax = s[i][0];
#pragma unroll
            for (int j = 1; j < 4; j++) tmax = fmaxf(tmax, s[i][j]);
#pragma unroll
            for (int off = 1; off < 16; off <<= 1)
                tmax = fmaxf(tmax, __shfl_xor_sync(0xffffffffu, tmax, off));

            const float mnew = fmaxf(m_i[i], tmax);
            const float sc = __expf(m_i[i] - mnew);
            m_i[i] = mnew;

            float tsum = 0.f;
#pragma unroll
            for (int j = 0; j < 4; j++) {
                const float p = __expf(s[i][j] - mnew);
                s[i][j] = p;
                tsum += p;
            }
#pragma unroll
            for (int off = 1; off < 16; off <<= 1)
                tsum += __shfl_xor_sync(0xffffffffu, tsum, off);

            l_i[i] = l_i[i] * sc + tsum;
#pragma unroll
            for (int j = 0; j < 4; j++) {
                o[i][j] *= sc;
                Ks[(r0 + i) * 65 + (c0 + j)] = s[i][j];
            }
        }
        __syncthreads();

        for (int kk = 0; kk < 64; kk++) {
            float af[4], bf[4];
#pragma unroll
            for (int i = 0; i < 4; i++) af[i] = Ks[(r0 + i) * 65 + kk];
#pragma unroll
            for (int j = 0; j < 4; j++) bf[j] = Vs[kk * 64 + c0 + j];
#pragma unroll
            for (int i = 0; i < 4; i++)
#pragma unroll
                for (int j = 0; j < 4; j++) o[i][j] += af[i] * bf[j];
        }
    }

    const int b = head >> 4;
    const int h = head & 15;
#pragma unroll
    for (int i = 0; i < 4; i++) {
        const int t = qt * 64 + r0 + i;
        const float inv = 1.f / l_i[i];
#pragma unroll
        for (int j = 0; j < 4; j++)
            g_y[(b * Tsz + t) * Csz + h * 64 + c0 + j] = o[i][j] * inv;
    }
}

// ---------------------------------------------------------------------------

extern "C" void kernel_launch(void* const* d_in, const int* in_sizes, int n_in,
                              void* d_out, int out_size)
{
    (void)in_sizes; (void)n_in; (void)out_size;
    const float* x      = (const float*)d_in[0];
    const float* w_attn = (const float*)d_in[1];
    const float* b_attn = (const float*)d_in[2];
    const float* w_proj = (const float*)d_in[3];
    const float* b_proj = (const float*)d_in[4];
    float* out = (float*)d_out;

    static const size_t ATTN_SMEM = (64 * 64 + 64 * 65 + 64 * 64) * sizeof(float);
    cudaFuncSetAttribute(attn_kernel,
                         cudaFuncAttributeMaxDynamicSharedMemorySize,
                         (int)ATTN_SMEM);

    qkv_gemm<<<dim3(N3 / 128, BT / 128), 256>>>(x, w_attn, b_attn);
    attn_kernel<<<dim3(Tsz / 64, Bsz * Hn), 256, ATTN_SMEM>>>();
    proj_gemm<<<dim3(Csz / 128, BT / 128), 256>>>(w_proj, b_proj, out);
}